// round 1
// baseline (speedup 1.0000x reference)
#include <cuda_runtime.h>
#include <math.h>

// ---------------------------------------------------------------------------
// GAT 4-layer stack on GB300.
// Layers: (256 -> 4x128 concat) -> (512 -> 4x128 concat) -> (512 -> 4x64 concat)
//         -> (256 -> 1x64, concat=False), ReLU after each.
// N = 30000 nodes, 480000 edges + 30000 self loops = 510000 edges.
// ---------------------------------------------------------------------------

#define NN      30000
#define E_RAW   480000
#define E_TOT   (E_RAW + NN)
#define MAXF    512
#define NEG_SLOPE 0.2f

// ---- scratch (device globals: no allocation allowed) ----------------------
__device__ float g_bufA[NN * MAXF];
__device__ float g_bufB[NN * MAXF];
__device__ float g_bufC[NN * MAXF];
__device__ float g_as[NN * 4];
__device__ float g_ad[NN * 4];
__device__ float g_alpha[(size_t)E_TOT * 4];
__device__ int   g_deg[NN];
__device__ int   g_rowptr[NN + 1];
__device__ int   g_cursor[NN];
__device__ int   g_csrsrc[E_TOT];
__device__ int   g_is64;

// ---------------------------------------------------------------------------
// edge_index dtype detection: jax may emit int32 (default) or int64 (x64 on).
// For int64, every node id < 30000 => high 32-bit word == 0. For int32 data
// interpreted the same way, "high words" are random node ids: ~never all zero.
// ---------------------------------------------------------------------------
__global__ void detect64_kernel(const int* __restrict__ words, int* flag) {
    if (threadIdx.x == 0 && blockIdx.x == 0) {
        int any = 0;
        #pragma unroll 4
        for (int i = 0; i < 256; i++) any |= words[2 * i + 1];
        *flag = (any == 0) ? 1 : 0;
    }
}

__device__ __forceinline__ void get_edge(const void* ei, int e, int is64,
                                         int& src, int& dst) {
    if (e >= E_RAW) {               // appended self loop
        src = dst = e - E_RAW;
        return;
    }
    if (is64) {
        const long long* p = (const long long*)ei;
        src = (int)p[e];
        dst = (int)p[E_RAW + e];
    } else {
        const int* p = (const int*)ei;
        src = p[e];
        dst = p[E_RAW + e];
    }
}

// ---- CSR build ------------------------------------------------------------
__global__ void count_deg_kernel(const void* __restrict__ ei,
                                 const int* __restrict__ flag,
                                 int* __restrict__ deg) {
    int e = blockIdx.x * blockDim.x + threadIdx.x;
    if (e >= E_TOT) return;
    int is64 = *flag;
    int src, dst;
    get_edge(ei, e, is64, src, dst);
    atomicAdd(&deg[dst], 1);
}

__global__ void scan_kernel(const int* __restrict__ deg,
                            int* __restrict__ rowptr, int n) {
    __shared__ int sh[1024];
    __shared__ int carry_s;
    int t = threadIdx.x;
    if (t == 0) carry_s = 0;
    __syncthreads();
    for (int base = 0; base < n; base += 1024) {
        int i = base + t;
        int v = (i < n) ? deg[i] : 0;
        sh[t] = v;
        __syncthreads();
        for (int off = 1; off < 1024; off <<= 1) {
            int u = (t >= off) ? sh[t - off] : 0;
            __syncthreads();
            sh[t] += u;
            __syncthreads();
        }
        int carry = carry_s;
        if (i < n) rowptr[i] = carry + sh[t] - v;   // exclusive scan
        __syncthreads();
        if (t == 1023) carry_s = carry + sh[1023];
        __syncthreads();
    }
    if (t == 0) rowptr[n] = carry_s;
}

__global__ void fill_csr_kernel(const void* __restrict__ ei,
                                const int* __restrict__ flag,
                                int* __restrict__ cursor,
                                int* __restrict__ csrsrc) {
    int e = blockIdx.x * blockDim.x + threadIdx.x;
    if (e >= E_TOT) return;
    int is64 = *flag;
    int src, dst;
    get_edge(ei, e, is64, src, dst);
    int pos = atomicAdd(&cursor[dst], 1);
    csrsrc[pos] = src;
}

// ---- SGEMM: C = A[MxK] * B[KxN], row-major, fp32 --------------------------
#define BM 128
#define BN 128
#define BK 16
#define TM 8
#define TN 8

__global__ __launch_bounds__(256)
void sgemm_kernel(const float* __restrict__ A, const float* __restrict__ B,
                  float* __restrict__ C, int M, int N, int K) {
    __shared__ float As[BK][BM];
    __shared__ float Bs[BK][BN];

    int tid = threadIdx.x;
    int bm = blockIdx.y * BM;
    int bn = blockIdx.x * BN;

    int tr = (tid / 16) * TM;
    int tc = (tid % 16) * TN;

    float acc[TM][TN];
    #pragma unroll
    for (int i = 0; i < TM; i++)
        #pragma unroll
        for (int j = 0; j < TN; j++) acc[i][j] = 0.f;

    int a_row0 = tid / 4;           // 0..63, two passes (stride 64)
    int a_col0 = (tid % 4) * 4;     // 0,4,8,12
    int b_row0 = tid / 32;          // 0..7, two passes (stride 8)
    int b_col0 = (tid % 32) * 4;    // 0..124

    for (int k0 = 0; k0 < K; k0 += BK) {
        #pragma unroll
        for (int i = 0; i < 2; i++) {
            int r = a_row0 + i * 64;
            int grow = bm + r;
            float4 v = make_float4(0.f, 0.f, 0.f, 0.f);
            if (grow < M)
                v = *(const float4*)&A[(size_t)grow * K + k0 + a_col0];
            As[a_col0 + 0][r] = v.x;
            As[a_col0 + 1][r] = v.y;
            As[a_col0 + 2][r] = v.z;
            As[a_col0 + 3][r] = v.w;
        }
        #pragma unroll
        for (int i = 0; i < 2; i++) {
            int r = b_row0 + i * 8;
            int gcol = bn + b_col0;
            float4 v = make_float4(0.f, 0.f, 0.f, 0.f);
            if (gcol < N)
                v = *(const float4*)&B[(size_t)(k0 + r) * N + gcol];
            *(float4*)&Bs[r][b_col0] = v;
        }
        __syncthreads();

        #pragma unroll
        for (int kk = 0; kk < BK; kk++) {
            float ar[TM], br[TN];
            #pragma unroll
            for (int i = 0; i < TM; i++) ar[i] = As[kk][tr + i];
            #pragma unroll
            for (int j = 0; j < TN; j++) br[j] = Bs[kk][tc + j];
            #pragma unroll
            for (int i = 0; i < TM; i++)
                #pragma unroll
                for (int j = 0; j < TN; j++)
                    acc[i][j] = fmaf(ar[i], br[j], acc[i][j]);
        }
        __syncthreads();
    }

    #pragma unroll
    for (int i = 0; i < TM; i++) {
        int grow = bm + tr + i;
        if (grow >= M) continue;
        #pragma unroll
        for (int j = 0; j < TN; j += 4) {
            int gcol = bn + tc + j;
            if (gcol < N) {
                float4 v = make_float4(acc[i][j], acc[i][j + 1],
                                       acc[i][j + 2], acc[i][j + 3]);
                *(float4*)&C[(size_t)grow * N + gcol] = v;
            }
        }
    }
}

// ---- per-node attention logits: as[n,h] = <h[n,h,:], a_s[h,:]>, same a_d --
__global__ void node_alpha_kernel(const float* __restrict__ h,
                                  const float* __restrict__ a_s,
                                  const float* __restrict__ a_d,
                                  float* __restrict__ out_s,
                                  float* __restrict__ out_d,
                                  int H, int C) {
    int warp = (blockIdx.x * blockDim.x + threadIdx.x) >> 5;
    int lane = threadIdx.x & 31;
    if (warp >= NN * H) return;
    int n = warp / H;
    int hd = warp - n * H;
    const float* hp = h + (size_t)n * H * C + (size_t)hd * C;
    const float* asv = a_s + (size_t)hd * C;
    const float* adv = a_d + (size_t)hd * C;
    float s = 0.f, d = 0.f;
    for (int c = lane; c < C; c += 32) {
        float v = hp[c];
        s = fmaf(v, asv[c], s);
        d = fmaf(v, adv[c], d);
    }
    #pragma unroll
    for (int o = 16; o > 0; o >>= 1) {
        s += __shfl_xor_sync(0xffffffffu, s, o);
        d += __shfl_xor_sync(0xffffffffu, d, o);
    }
    if (lane == 0) {
        out_s[n * H + hd] = s;
        out_d[n * H + hd] = d;
    }
}

// ---- edge softmax over incoming edges of each dst (warp per dst,head) -----
__device__ __forceinline__ float leaky(float x) {
    return x > 0.f ? x : NEG_SLOPE * x;
}

__global__ void edge_softmax_kernel(const int* __restrict__ rowptr,
                                    const int* __restrict__ csrsrc,
                                    const float* __restrict__ as_,
                                    const float* __restrict__ ad_,
                                    float* __restrict__ alpha, int H) {
    int warp = (blockIdx.x * blockDim.x + threadIdx.x) >> 5;
    int lane = threadIdx.x & 31;
    if (warp >= NN * H) return;
    int d = warp / H;
    int hd = warp - d * H;
    int s0 = rowptr[d], s1 = rowptr[d + 1];
    float adv = ad_[d * H + hd];

    float mx = -3.0e38f;
    for (int p = s0 + lane; p < s1; p += 32) {
        float e = leaky(as_[csrsrc[p] * H + hd] + adv);
        mx = fmaxf(mx, e);
    }
    #pragma unroll
    for (int o = 16; o > 0; o >>= 1)
        mx = fmaxf(mx, __shfl_xor_sync(0xffffffffu, mx, o));

    float sum = 0.f;
    for (int p = s0 + lane; p < s1; p += 32) {
        float e = leaky(as_[csrsrc[p] * H + hd] + adv);
        float ex = expf(e - mx);
        alpha[(size_t)p * H + hd] = ex;
        sum += ex;
    }
    #pragma unroll
    for (int o = 16; o > 0; o >>= 1)
        sum += __shfl_xor_sync(0xffffffffu, sum, o);
    float inv = 1.f / sum;

    for (int p = s0 + lane; p < s1; p += 32)
        alpha[(size_t)p * H + hd] *= inv;
}

// ---- aggregation: out[d] = relu(sum_e alpha[e]*h[src_e] + bias) -----------
// block per dst node, float4 per thread, register accumulation (no atomics).
__global__ __launch_bounds__(128)
void aggregate_kernel(const float* __restrict__ h,
                      const float* __restrict__ alpha,
                      const int* __restrict__ rowptr,
                      const int* __restrict__ csrsrc,
                      const float* __restrict__ bias,
                      float* __restrict__ out,
                      int H, int HC, int logC) {
    int d = blockIdx.x;
    int f = threadIdx.x * 4;
    if (f >= HC) return;
    int head = f >> logC;

    float4 acc = make_float4(0.f, 0.f, 0.f, 0.f);
    int s0 = rowptr[d], s1 = rowptr[d + 1];
    for (int p = s0; p < s1; p++) {
        int src = csrsrc[p];
        float a = alpha[(size_t)p * H + head];
        float4 v = *(const float4*)&h[(size_t)src * HC + f];
        acc.x = fmaf(v.x, a, acc.x);
        acc.y = fmaf(v.y, a, acc.y);
        acc.z = fmaf(v.z, a, acc.z);
        acc.w = fmaf(v.w, a, acc.w);
    }
    float4 b = *(const float4*)&bias[f];
    float4 o;
    o.x = fmaxf(acc.x + b.x, 0.f);
    o.y = fmaxf(acc.y + b.y, 0.f);
    o.z = fmaxf(acc.z + b.z, 0.f);
    o.w = fmaxf(acc.w + b.w, 0.f);
    *(float4*)&out[(size_t)d * HC + f] = o;
}

// ---------------------------------------------------------------------------
// host side
// ---------------------------------------------------------------------------
static inline void run_gemm(const float* A, const float* B, float* C,
                            int M, int N, int K) {
    dim3 grid((N + BN - 1) / BN, (M + BM - 1) / BM);
    sgemm_kernel<<<grid, 256>>>(A, B, C, M, N, K);
}

extern "C" void kernel_launch(void* const* d_in, const int* in_sizes, int n_in,
                              void* d_out, int out_size) {
    const float* x   = (const float*)d_in[0];
    const void*  ei  = d_in[1];
    const float* W1  = (const float*)d_in[2];
    const float* a1s = (const float*)d_in[3];
    const float* a1d = (const float*)d_in[4];
    const float* b1  = (const float*)d_in[5];
    const float* W2  = (const float*)d_in[6];
    const float* a2s = (const float*)d_in[7];
    const float* a2d = (const float*)d_in[8];
    const float* b2  = (const float*)d_in[9];
    const float* W3  = (const float*)d_in[10];
    const float* a3s = (const float*)d_in[11];
    const float* a3d = (const float*)d_in[12];
    const float* b3  = (const float*)d_in[13];
    const float* W4  = (const float*)d_in[14];
    const float* a4s = (const float*)d_in[15];
    const float* a4d = (const float*)d_in[16];
    const float* b4  = (const float*)d_in[17];
    float* out = (float*)d_out;

    float *bufA, *bufB, *bufC, *asb, *adb, *alpha;
    int *deg, *rowptr, *cursor, *csrsrc, *is64;
    cudaGetSymbolAddress((void**)&bufA, g_bufA);
    cudaGetSymbolAddress((void**)&bufB, g_bufB);
    cudaGetSymbolAddress((void**)&bufC, g_bufC);
    cudaGetSymbolAddress((void**)&asb, g_as);
    cudaGetSymbolAddress((void**)&adb, g_ad);
    cudaGetSymbolAddress((void**)&alpha, g_alpha);
    cudaGetSymbolAddress((void**)&deg, g_deg);
    cudaGetSymbolAddress((void**)&rowptr, g_rowptr);
    cudaGetSymbolAddress((void**)&cursor, g_cursor);
    cudaGetSymbolAddress((void**)&csrsrc, g_csrsrc);
    cudaGetSymbolAddress((void**)&is64, g_is64);

    // ---- CSR build (graph identical for all 4 layers) ----
    cudaMemsetAsync(deg, 0, NN * sizeof(int));
    detect64_kernel<<<1, 32>>>((const int*)ei, is64);
    count_deg_kernel<<<(E_TOT + 255) / 256, 256>>>(ei, is64, deg);
    scan_kernel<<<1, 1024>>>(deg, rowptr, NN);
    cudaMemcpyAsync(cursor, rowptr, NN * sizeof(int),
                    cudaMemcpyDeviceToDevice);
    fill_csr_kernel<<<(E_TOT + 255) / 256, 256>>>(ei, is64, cursor, csrsrc);

    const int warpsPerBlock = 8;  // 256 threads
    auto nblocks_warps = [](int warps) {
        return (warps + 7) / 8;
    };

    // ---- layer 1: 256 -> 4x128 ----
    run_gemm(x, W1, bufB, NN, 512, 256);
    node_alpha_kernel<<<nblocks_warps(NN * 4), 256>>>(bufB, a1s, a1d, asb, adb, 4, 128);
    edge_softmax_kernel<<<nblocks_warps(NN * 4), 256>>>(rowptr, csrsrc, asb, adb, alpha, 4);
    aggregate_kernel<<<NN, 128>>>(bufB, alpha, rowptr, csrsrc, b1, bufC, 4, 512, 7);

    // ---- layer 2: 512 -> 4x128 ----
    run_gemm(bufC, W2, bufB, NN, 512, 512);
    node_alpha_kernel<<<nblocks_warps(NN * 4), 256>>>(bufB, a2s, a2d, asb, adb, 4, 128);
    edge_softmax_kernel<<<nblocks_warps(NN * 4), 256>>>(rowptr, csrsrc, asb, adb, alpha, 4);
    aggregate_kernel<<<NN, 128>>>(bufB, alpha, rowptr, csrsrc, b2, bufA, 4, 512, 7);

    // ---- layer 3: 512 -> 4x64 ----
    run_gemm(bufA, W3, bufB, NN, 256, 512);
    node_alpha_kernel<<<nblocks_warps(NN * 4), 256>>>(bufB, a3s, a3d, asb, adb, 4, 64);
    edge_softmax_kernel<<<nblocks_warps(NN * 4), 256>>>(rowptr, csrsrc, asb, adb, alpha, 4);
    aggregate_kernel<<<NN, 128>>>(bufB, alpha, rowptr, csrsrc, b3, bufC, 4, 256, 6);

    // ---- layer 4: 256 -> 1x64, concat=False (mean over 1 head == identity) ----
    run_gemm(bufC, W4, bufB, NN, 64, 256);
    node_alpha_kernel<<<nblocks_warps(NN * 1), 256>>>(bufB, a4s, a4d, asb, adb, 1, 64);
    edge_softmax_kernel<<<nblocks_warps(NN * 1), 256>>>(rowptr, csrsrc, asb, adb, alpha, 1);
    aggregate_kernel<<<NN, 128>>>(bufB, alpha, rowptr, csrsrc, b4, out, 1, 64, 6);

    (void)in_sizes; (void)n_in; (void)out_size;
}

// round 2
// speedup vs baseline: 1.7326x; 1.7326x over previous
#include <cuda_runtime.h>
#include <math.h>

// ---------------------------------------------------------------------------
// GAT 4-layer stack on GB300, round 2: TF32 tensor-core GEMM (mma.sync m16n8k8)
// N = 30000 nodes, 480000 edges + 30000 self loops = 510000 edges.
// ---------------------------------------------------------------------------

#define NN      30000
#define E_RAW   480000
#define E_TOT   (E_RAW + NN)
#define MAXF    512
#define NEG_SLOPE 0.2f

// ---- scratch (device globals: no allocation allowed) ----------------------
__device__ float g_bufA[NN * MAXF];
__device__ float g_bufB[NN * MAXF];
__device__ float g_bufC[NN * MAXF];
__device__ float g_as[NN * 4];
__device__ float g_ad[NN * 4];
__device__ float g_alpha[(size_t)E_TOT * 4];
__device__ int   g_deg[NN];
__device__ int   g_rowptr[NN + 1];
__device__ int   g_cursor[NN];
__device__ int   g_csrsrc[E_TOT];
__device__ int   g_is64;

// ---------------------------------------------------------------------------
// edge_index dtype detection (int32 vs int64)
// ---------------------------------------------------------------------------
__global__ void detect64_kernel(const int* __restrict__ words, int* flag) {
    if (threadIdx.x == 0 && blockIdx.x == 0) {
        int any = 0;
        #pragma unroll 4
        for (int i = 0; i < 256; i++) any |= words[2 * i + 1];
        *flag = (any == 0) ? 1 : 0;
    }
}

__device__ __forceinline__ void get_edge(const void* ei, int e, int is64,
                                         int& src, int& dst) {
    if (e >= E_RAW) {               // appended self loop
        src = dst = e - E_RAW;
        return;
    }
    if (is64) {
        const long long* p = (const long long*)ei;
        src = (int)p[e];
        dst = (int)p[E_RAW + e];
    } else {
        const int* p = (const int*)ei;
        src = p[e];
        dst = p[E_RAW + e];
    }
}

// ---- CSR build ------------------------------------------------------------
__global__ void count_deg_kernel(const void* __restrict__ ei,
                                 const int* __restrict__ flag,
                                 int* __restrict__ deg) {
    int e = blockIdx.x * blockDim.x + threadIdx.x;
    if (e >= E_TOT) return;
    int is64 = *flag;
    int src, dst;
    get_edge(ei, e, is64, src, dst);
    atomicAdd(&deg[dst], 1);
}

__global__ void scan_kernel(const int* __restrict__ deg,
                            int* __restrict__ rowptr, int n) {
    __shared__ int sh[1024];
    __shared__ int carry_s;
    int t = threadIdx.x;
    if (t == 0) carry_s = 0;
    __syncthreads();
    for (int base = 0; base < n; base += 1024) {
        int i = base + t;
        int v = (i < n) ? deg[i] : 0;
        sh[t] = v;
        __syncthreads();
        for (int off = 1; off < 1024; off <<= 1) {
            int u = (t >= off) ? sh[t - off] : 0;
            __syncthreads();
            sh[t] += u;
            __syncthreads();
        }
        int carry = carry_s;
        if (i < n) rowptr[i] = carry + sh[t] - v;   // exclusive scan
        __syncthreads();
        if (t == 1023) carry_s = carry + sh[1023];
        __syncthreads();
    }
    if (t == 0) rowptr[n] = carry_s;
}

__global__ void fill_csr_kernel(const void* __restrict__ ei,
                                const int* __restrict__ flag,
                                int* __restrict__ cursor,
                                int* __restrict__ csrsrc) {
    int e = blockIdx.x * blockDim.x + threadIdx.x;
    if (e >= E_TOT) return;
    int is64 = *flag;
    int src, dst;
    get_edge(ei, e, is64, src, dst);
    int pos = atomicAdd(&cursor[dst], 1);
    csrsrc[pos] = src;
}

// ---------------------------------------------------------------------------
// TF32 tensor-core GEMM: C = A[MxK] * B[KxN], row-major fp32 in/out.
// Block tile 128x128x32, 8 warps (2x4), warp tile 64x32, mma m16n8k8.
// Smem: A m-major stride 36 (bank=(4m+k)%32 bijective over fragment lanes),
//       B k-major stride 136 (bank=(8k+n)%32 bijective). Zero conflicts.
// ---------------------------------------------------------------------------
#define TBM 128
#define TBN 128
#define TBK 32
#define SA  36
#define SB  136

__device__ __forceinline__ unsigned f2tf32(float x) {
    unsigned u;
    asm("cvt.rna.tf32.f32 %0, %1;" : "=r"(u) : "f"(x));
    return u;
}

__device__ __forceinline__ void mma_tf32(float* d, const unsigned* a,
                                         const unsigned* b) {
    asm volatile(
        "mma.sync.aligned.m16n8k8.row.col.f32.tf32.tf32.f32 "
        "{%0,%1,%2,%3}, {%4,%5,%6,%7}, {%8,%9}, {%0,%1,%2,%3};\n"
        : "+f"(d[0]), "+f"(d[1]), "+f"(d[2]), "+f"(d[3])
        : "r"(a[0]), "r"(a[1]), "r"(a[2]), "r"(a[3]),
          "r"(b[0]), "r"(b[1]));
}

__global__ __launch_bounds__(256)
void tf32gemm_kernel(const float* __restrict__ A, const float* __restrict__ B,
                     float* __restrict__ C, int M, int N, int K) {
    __shared__ float As[TBM * SA];   // 18432 B
    __shared__ float Bs[TBK * SB];   // 17408 B

    int tid  = threadIdx.x;
    int bm   = blockIdx.y * TBM;
    int bn   = blockIdx.x * TBN;
    int warp = tid >> 5;
    int lane = tid & 31;
    int wm   = (warp & 1) * 64;      // warp m offset
    int wn   = (warp >> 1) * 32;     // warp n offset
    int r    = lane >> 2;            // 0..7
    int c    = lane & 3;             // 0..3

    float acc[4][4][4];
    #pragma unroll
    for (int mi = 0; mi < 4; mi++)
        #pragma unroll
        for (int ni = 0; ni < 4; ni++)
            #pragma unroll
            for (int q = 0; q < 4; q++) acc[mi][ni][q] = 0.f;

    int a_r = tid >> 3;              // 0..31
    int a_c = (tid & 7) * 4;         // 0..28
    int b_r = tid >> 5;              // 0..7
    int b_c = (tid & 31) * 4;        // 0..124

    for (int k0 = 0; k0 < K; k0 += TBK) {
        // stage A tile (convert to tf32 on the way in)
        #pragma unroll
        for (int i = 0; i < 4; i++) {
            int m  = a_r + i * 32;
            int gm = bm + m;
            float4 v = make_float4(0.f, 0.f, 0.f, 0.f);
            if (gm < M)
                v = *(const float4*)&A[(size_t)gm * K + k0 + a_c];
            uint4 u;
            u.x = f2tf32(v.x); u.y = f2tf32(v.y);
            u.z = f2tf32(v.z); u.w = f2tf32(v.w);
            *(uint4*)&As[m * SA + a_c] = u;
        }
        // stage B tile
        #pragma unroll
        for (int i = 0; i < 4; i++) {
            int kr = b_r + i * 8;
            int gn = bn + b_c;
            float4 v = make_float4(0.f, 0.f, 0.f, 0.f);
            if (gn < N)
                v = *(const float4*)&B[(size_t)(k0 + kr) * N + gn];
            uint4 u;
            u.x = f2tf32(v.x); u.y = f2tf32(v.y);
            u.z = f2tf32(v.z); u.w = f2tf32(v.w);
            *(uint4*)&Bs[kr * SB + b_c] = u;
        }
        __syncthreads();

        #pragma unroll
        for (int kk = 0; kk < 4; kk++) {
            int k8 = kk * 8;
            unsigned af[4][4];
            #pragma unroll
            for (int mi = 0; mi < 4; mi++) {
                const float* ap = &As[(wm + mi * 16 + r) * SA + k8 + c];
                af[mi][0] = __float_as_uint(ap[0]);
                af[mi][1] = __float_as_uint(ap[8 * SA]);
                af[mi][2] = __float_as_uint(ap[4]);
                af[mi][3] = __float_as_uint(ap[8 * SA + 4]);
            }
            unsigned bf[4][2];
            #pragma unroll
            for (int ni = 0; ni < 4; ni++) {
                const float* bp = &Bs[(k8 + c) * SB + wn + ni * 8 + r];
                bf[ni][0] = __float_as_uint(bp[0]);
                bf[ni][1] = __float_as_uint(bp[4 * SB]);
            }
            #pragma unroll
            for (int mi = 0; mi < 4; mi++)
                #pragma unroll
                for (int ni = 0; ni < 4; ni++)
                    mma_tf32(acc[mi][ni], af[mi], bf[ni]);
        }
        __syncthreads();
    }

    // epilogue: float2 stores, cols even so always in-bounds pairs
    #pragma unroll
    for (int mi = 0; mi < 4; mi++) {
        int m0 = bm + wm + mi * 16 + r;
        #pragma unroll
        for (int ni = 0; ni < 4; ni++) {
            int n0 = bn + wn + ni * 8 + 2 * c;
            if (n0 < N) {
                if (m0 < M) {
                    float2 v = make_float2(acc[mi][ni][0], acc[mi][ni][1]);
                    *(float2*)&C[(size_t)m0 * N + n0] = v;
                }
                if (m0 + 8 < M) {
                    float2 v = make_float2(acc[mi][ni][2], acc[mi][ni][3]);
                    *(float2*)&C[(size_t)(m0 + 8) * N + n0] = v;
                }
            }
        }
    }
}

// ---- per-node attention logits -------------------------------------------
__global__ void node_alpha_kernel(const float* __restrict__ h,
                                  const float* __restrict__ a_s,
                                  const float* __restrict__ a_d,
                                  float* __restrict__ out_s,
                                  float* __restrict__ out_d,
                                  int H, int C) {
    int warp = (blockIdx.x * blockDim.x + threadIdx.x) >> 5;
    int lane = threadIdx.x & 31;
    if (warp >= NN * H) return;
    int n = warp / H;
    int hd = warp - n * H;
    const float* hp = h + (size_t)n * H * C + (size_t)hd * C;
    const float* asv = a_s + (size_t)hd * C;
    const float* adv = a_d + (size_t)hd * C;
    float s = 0.f, d = 0.f;
    for (int cc = lane; cc < C; cc += 32) {
        float v = hp[cc];
        s = fmaf(v, asv[cc], s);
        d = fmaf(v, adv[cc], d);
    }
    #pragma unroll
    for (int o = 16; o > 0; o >>= 1) {
        s += __shfl_xor_sync(0xffffffffu, s, o);
        d += __shfl_xor_sync(0xffffffffu, d, o);
    }
    if (lane == 0) {
        out_s[n * H + hd] = s;
        out_d[n * H + hd] = d;
    }
}

// ---- edge softmax (warp per dst,head) -------------------------------------
__device__ __forceinline__ float leaky(float x) {
    return x > 0.f ? x : NEG_SLOPE * x;
}

__global__ void edge_softmax_kernel(const int* __restrict__ rowptr,
                                    const int* __restrict__ csrsrc,
                                    const float* __restrict__ as_,
                                    const float* __restrict__ ad_,
                                    float* __restrict__ alpha, int H) {
    int warp = (blockIdx.x * blockDim.x + threadIdx.x) >> 5;
    int lane = threadIdx.x & 31;
    if (warp >= NN * H) return;
    int d = warp / H;
    int hd = warp - d * H;
    int s0 = rowptr[d], s1 = rowptr[d + 1];
    float adv = ad_[d * H + hd];

    float mx = -3.0e38f;
    for (int p = s0 + lane; p < s1; p += 32) {
        float e = leaky(as_[csrsrc[p] * H + hd] + adv);
        mx = fmaxf(mx, e);
    }
    #pragma unroll
    for (int o = 16; o > 0; o >>= 1)
        mx = fmaxf(mx, __shfl_xor_sync(0xffffffffu, mx, o));

    float sum = 0.f;
    for (int p = s0 + lane; p < s1; p += 32) {
        float e = leaky(as_[csrsrc[p] * H + hd] + adv);
        float ex = expf(e - mx);
        alpha[(size_t)p * H + hd] = ex;
        sum += ex;
    }
    #pragma unroll
    for (int o = 16; o > 0; o >>= 1)
        sum += __shfl_xor_sync(0xffffffffu, sum, o);
    float inv = 1.f / sum;

    for (int p = s0 + lane; p < s1; p += 32)
        alpha[(size_t)p * H + hd] *= inv;
}

// ---- aggregation ----------------------------------------------------------
// blockDim.x = HC/4 (one float4 per thread), blockDim.y dsts per block.
__global__ __launch_bounds__(256)
void aggregate_kernel(const float* __restrict__ h,
                      const float* __restrict__ alpha,
                      const int* __restrict__ rowptr,
                      const int* __restrict__ csrsrc,
                      const float* __restrict__ bias,
                      float* __restrict__ out,
                      int H, int HC, int logC) {
    int d = blockIdx.x * blockDim.y + threadIdx.y;
    if (d >= NN) return;
    int f = threadIdx.x * 4;
    int head = f >> logC;

    float4 acc = make_float4(0.f, 0.f, 0.f, 0.f);
    int s0 = rowptr[d], s1 = rowptr[d + 1];
    for (int p = s0; p < s1; p++) {
        int src = csrsrc[p];
        float a = alpha[(size_t)p * H + head];
        float4 v = *(const float4*)&h[(size_t)src * HC + f];
        acc.x = fmaf(v.x, a, acc.x);
        acc.y = fmaf(v.y, a, acc.y);
        acc.z = fmaf(v.z, a, acc.z);
        acc.w = fmaf(v.w, a, acc.w);
    }
    float4 b = *(const float4*)&bias[f];
    float4 o;
    o.x = fmaxf(acc.x + b.x, 0.f);
    o.y = fmaxf(acc.y + b.y, 0.f);
    o.z = fmaxf(acc.z + b.z, 0.f);
    o.w = fmaxf(acc.w + b.w, 0.f);
    *(float4*)&out[(size_t)d * HC + f] = o;
}

// ---------------------------------------------------------------------------
// host side
// ---------------------------------------------------------------------------
static inline void run_gemm(const float* A, const float* B, float* C,
                            int M, int N, int K) {
    dim3 grid((N + TBN - 1) / TBN, (M + TBM - 1) / TBM);
    tf32gemm_kernel<<<grid, 256>>>(A, B, C, M, N, K);
}

static inline void run_aggregate(const float* h, const float* alpha,
                                 const int* rowptr, const int* csrsrc,
                                 const float* bias, float* out,
                                 int H, int HC, int logC) {
    int tx = HC / 4;
    int ty = 256 / tx;
    dim3 block(tx, ty);
    dim3 grid((NN + ty - 1) / ty);
    aggregate_kernel<<<grid, block>>>(h, alpha, rowptr, csrsrc, bias, out,
                                      H, HC, logC);
}

extern "C" void kernel_launch(void* const* d_in, const int* in_sizes, int n_in,
                              void* d_out, int out_size) {
    const float* x   = (const float*)d_in[0];
    const void*  ei  = d_in[1];
    const float* W1  = (const float*)d_in[2];
    const float* a1s = (const float*)d_in[3];
    const float* a1d = (const float*)d_in[4];
    const float* b1  = (const float*)d_in[5];
    const float* W2  = (const float*)d_in[6];
    const float* a2s = (const float*)d_in[7];
    const float* a2d = (const float*)d_in[8];
    const float* b2  = (const float*)d_in[9];
    const float* W3  = (const float*)d_in[10];
    const float* a3s = (const float*)d_in[11];
    const float* a3d = (const float*)d_in[12];
    const float* b3  = (const float*)d_in[13];
    const float* W4  = (const float*)d_in[14];
    const float* a4s = (const float*)d_in[15];
    const float* a4d = (const float*)d_in[16];
    const float* b4  = (const float*)d_in[17];
    float* out = (float*)d_out;

    float *bufA, *bufB, *bufC, *asb, *adb, *alpha;
    int *deg, *rowptr, *cursor, *csrsrc, *is64;
    cudaGetSymbolAddress((void**)&bufA, g_bufA);
    cudaGetSymbolAddress((void**)&bufB, g_bufB);
    cudaGetSymbolAddress((void**)&bufC, g_bufC);
    cudaGetSymbolAddress((void**)&asb, g_as);
    cudaGetSymbolAddress((void**)&adb, g_ad);
    cudaGetSymbolAddress((void**)&alpha, g_alpha);
    cudaGetSymbolAddress((void**)&deg, g_deg);
    cudaGetSymbolAddress((void**)&rowptr, g_rowptr);
    cudaGetSymbolAddress((void**)&cursor, g_cursor);
    cudaGetSymbolAddress((void**)&csrsrc, g_csrsrc);
    cudaGetSymbolAddress((void**)&is64, g_is64);

    // ---- CSR build (graph identical for all 4 layers) ----
    cudaMemsetAsync(deg, 0, NN * sizeof(int));
    detect64_kernel<<<1, 32>>>((const int*)ei, is64);
    count_deg_kernel<<<(E_TOT + 255) / 256, 256>>>(ei, is64, deg);
    scan_kernel<<<1, 1024>>>(deg, rowptr, NN);
    cudaMemcpyAsync(cursor, rowptr, NN * sizeof(int),
                    cudaMemcpyDeviceToDevice);
    fill_csr_kernel<<<(E_TOT + 255) / 256, 256>>>(ei, is64, cursor, csrsrc);

    auto nblocks_warps = [](int warps) { return (warps + 7) / 8; };

    // ---- layer 1: 256 -> 4x128 ----
    run_gemm(x, W1, bufB, NN, 512, 256);
    node_alpha_kernel<<<nblocks_warps(NN * 4), 256>>>(bufB, a1s, a1d, asb, adb, 4, 128);
    edge_softmax_kernel<<<nblocks_warps(NN * 4), 256>>>(rowptr, csrsrc, asb, adb, alpha, 4);
    run_aggregate(bufB, alpha, rowptr, csrsrc, b1, bufC, 4, 512, 7);

    // ---- layer 2: 512 -> 4x128 ----
    run_gemm(bufC, W2, bufB, NN, 512, 512);
    node_alpha_kernel<<<nblocks_warps(NN * 4), 256>>>(bufB, a2s, a2d, asb, adb, 4, 128);
    edge_softmax_kernel<<<nblocks_warps(NN * 4), 256>>>(rowptr, csrsrc, asb, adb, alpha, 4);
    run_aggregate(bufB, alpha, rowptr, csrsrc, b2, bufA, 4, 512, 7);

    // ---- layer 3: 512 -> 4x64 ----
    run_gemm(bufA, W3, bufB, NN, 256, 512);
    node_alpha_kernel<<<nblocks_warps(NN * 4), 256>>>(bufB, a3s, a3d, asb, adb, 4, 64);
    edge_softmax_kernel<<<nblocks_warps(NN * 4), 256>>>(rowptr, csrsrc, asb, adb, alpha, 4);
    run_aggregate(bufB, alpha, rowptr, csrsrc, b3, bufC, 4, 256, 6);

    // ---- layer 4: 256 -> 1x64, concat=False (mean over 1 head == identity) ----
    run_gemm(bufC, W4, bufB, NN, 64, 256);
    node_alpha_kernel<<<nblocks_warps(NN * 1), 256>>>(bufB, a4s, a4d, asb, adb, 1, 64);
    edge_softmax_kernel<<<nblocks_warps(NN * 1), 256>>>(rowptr, csrsrc, asb, adb, alpha, 1);
    run_aggregate(bufB, alpha, rowptr, csrsrc, b4, out, 1, 64, 6);

    (void)in_sizes; (void)n_in; (void)out_size;
}

// round 4
// speedup vs baseline: 2.1140x; 1.2201x over previous
#include <cuda_runtime.h>
#include <cuda_fp16.h>
#include <cstdint>
#include <math.h>

// ---------------------------------------------------------------------------
// GAT 4-layer stack on GB300, round 4 (= round 3 + missing <cstdint>):
//  - fp16 mma.sync m16n8k16 GEMM (fp32 accum), cp.async double-buffered
//  - attention/softmax/aggregation stay fp32 (h is fp32)
//  - aggregate writes fp16 next-layer input (== tf32-equiv rounding)
// ---------------------------------------------------------------------------

#define NN      30000
#define E_RAW   480000
#define E_TOT   (E_RAW + NN)
#define MAXF    512
#define NEG_SLOPE 0.2f

// ---- scratch (device globals) ---------------------------------------------
__device__ float  g_bufB[NN * MAXF];            // fp32 h (GEMM output)
__device__ __half g_hA[NN * MAXF];              // fp16 activations ping
__device__ __half g_hB[NN * MAXF];              // fp16 activations pong
__device__ __half g_wt[540672];                 // all transposed fp16 weights
__device__ float  g_as[NN * 4];
__device__ float  g_ad[NN * 4];
__device__ float  g_alpha[(size_t)E_TOT * 4];
__device__ int    g_deg[NN];
__device__ int    g_rowptr[NN + 1];
__device__ int    g_cursor[NN];
__device__ int    g_csrsrc[E_TOT];
__device__ int    g_is64;

// ---------------------------------------------------------------------------
// edge_index dtype detection (int32 vs int64)
// ---------------------------------------------------------------------------
__global__ void detect64_kernel(const int* __restrict__ words, int* flag) {
    if (threadIdx.x == 0 && blockIdx.x == 0) {
        int any = 0;
        #pragma unroll 4
        for (int i = 0; i < 256; i++) any |= words[2 * i + 1];
        *flag = (any == 0) ? 1 : 0;
    }
}

__device__ __forceinline__ void get_edge(const void* ei, int e, int is64,
                                         int& src, int& dst) {
    if (e >= E_RAW) { src = dst = e - E_RAW; return; }
    if (is64) {
        const long long* p = (const long long*)ei;
        src = (int)p[e];
        dst = (int)p[E_RAW + e];
    } else {
        const int* p = (const int*)ei;
        src = p[e];
        dst = p[E_RAW + e];
    }
}

// ---- CSR build ------------------------------------------------------------
__global__ void count_deg_kernel(const void* __restrict__ ei,
                                 const int* __restrict__ flag,
                                 int* __restrict__ deg) {
    int e = blockIdx.x * blockDim.x + threadIdx.x;
    if (e >= E_TOT) return;
    int src, dst;
    get_edge(ei, e, *flag, src, dst);
    atomicAdd(&deg[dst], 1);
}

__global__ void scan_kernel(const int* __restrict__ deg,
                            int* __restrict__ rowptr, int n) {
    __shared__ int sh[1024];
    __shared__ int carry_s;
    int t = threadIdx.x;
    if (t == 0) carry_s = 0;
    __syncthreads();
    for (int base = 0; base < n; base += 1024) {
        int i = base + t;
        int v = (i < n) ? deg[i] : 0;
        sh[t] = v;
        __syncthreads();
        for (int off = 1; off < 1024; off <<= 1) {
            int u = (t >= off) ? sh[t - off] : 0;
            __syncthreads();
            sh[t] += u;
            __syncthreads();
        }
        int carry = carry_s;
        if (i < n) rowptr[i] = carry + sh[t] - v;
        __syncthreads();
        if (t == 1023) carry_s = carry + sh[1023];
        __syncthreads();
    }
    if (t == 0) rowptr[n] = carry_s;
}

__global__ void fill_csr_kernel(const void* __restrict__ ei,
                                const int* __restrict__ flag,
                                int* __restrict__ cursor,
                                int* __restrict__ csrsrc) {
    int e = blockIdx.x * blockDim.x + threadIdx.x;
    if (e >= E_TOT) return;
    int src, dst;
    get_edge(ei, e, *flag, src, dst);
    int pos = atomicAdd(&cursor[dst], 1);
    csrsrc[pos] = src;
}

// ---- prep: fp32 -> fp16 convert, weight transpose -------------------------
__global__ void f2h_kernel(const float* __restrict__ in,
                           __half* __restrict__ out, int n) {
    int i = blockIdx.x * blockDim.x + threadIdx.x;
    int i4 = i * 4;
    if (i4 + 3 < n) {
        float4 v = *(const float4*)&in[i4];
        __half2 lo = __floats2half2_rn(v.x, v.y);
        __half2 hi = __floats2half2_rn(v.z, v.w);
        *(__half2*)&out[i4] = lo;
        *(__half2*)&out[i4 + 2] = hi;
    } else {
        for (int j = i4; j < n; j++) out[j] = __float2half_rn(in[j]);
    }
}

// W[K][N] fp32 -> Wt[N][K] fp16
__global__ void transpose_w_kernel(const float* __restrict__ W,
                                   __half* __restrict__ Wt, int K, int N) {
    __shared__ float tile[32][33];
    int k0 = blockIdx.y * 32, n0 = blockIdx.x * 32;
    int tx = threadIdx.x, ty = threadIdx.y;   // 32 x 8
    for (int i = ty; i < 32; i += 8) {
        int k = k0 + i, n = n0 + tx;
        tile[i][tx] = (k < K && n < N) ? W[(size_t)k * N + n] : 0.f;
    }
    __syncthreads();
    for (int i = ty; i < 32; i += 8) {
        int n = n0 + i, k = k0 + tx;
        if (n < N && k < K)
            Wt[(size_t)n * K + k] = __float2half_rn(tile[tx][i]);
    }
}

// ---------------------------------------------------------------------------
// fp16 tensor-core GEMM: C[MxN] fp32 = A16[MxK] * Wt16[NxK]^T
// Block 128x128x32, 8 warps (2x4), warp tile 64x32, mma m16n8k16.
// Smem stride 40 halfs: fragment half2 loads hit word 20r+c — bijective mod 32.
// cp.async double-buffered staging.
// ---------------------------------------------------------------------------
#define TBM 128
#define TBN 128
#define TBK 32
#define SAH 40

__device__ __forceinline__ void cp16(unsigned int smem, const void* gptr, int sz) {
    asm volatile("cp.async.cg.shared.global [%0], [%1], 16, %2;\n"
                 :: "r"(smem), "l"(gptr), "r"(sz));
}

__device__ __forceinline__ unsigned int smem_u32(const void* p) {
    return (unsigned int)__cvta_generic_to_shared(p);
}

__device__ __forceinline__ void mma_f16(float* d, const unsigned* a,
                                        const unsigned* b) {
    asm volatile(
        "mma.sync.aligned.m16n8k16.row.col.f32.f16.f16.f32 "
        "{%0,%1,%2,%3}, {%4,%5,%6,%7}, {%8,%9}, {%0,%1,%2,%3};\n"
        : "+f"(d[0]), "+f"(d[1]), "+f"(d[2]), "+f"(d[3])
        : "r"(a[0]), "r"(a[1]), "r"(a[2]), "r"(a[3]),
          "r"(b[0]), "r"(b[1]));
}

__global__ __launch_bounds__(256, 2)
void h16gemm_kernel(const __half* __restrict__ A, const __half* __restrict__ Bt,
                    float* __restrict__ C, int M, int N, int K) {
    __shared__ __half As[2][TBM * SAH];
    __shared__ __half Bs[2][TBN * SAH];

    int tid  = threadIdx.x;
    int bm   = blockIdx.y * TBM;
    int bn   = blockIdx.x * TBN;
    int warp = tid >> 5;
    int lane = tid & 31;
    int wm   = (warp & 1) * 64;
    int wn   = (warp >> 1) * 32;
    int r    = lane >> 2;
    int c    = lane & 3;

    float acc[4][4][4];
    #pragma unroll
    for (int mi = 0; mi < 4; mi++)
        #pragma unroll
        for (int ni = 0; ni < 4; ni++)
            #pragma unroll
            for (int q = 0; q < 4; q++) acc[mi][ni][q] = 0.f;

    // staging: per tile, 128 rows x 2 chunks(16B) for A and same for B.
    int row0 = tid >> 1;                  // 0..127
    int kc0  = (tid & 1) * 2;             // 0 or 2

    int niter = K / TBK;

    auto stage = [&](int buf, int k0) {
        #pragma unroll
        for (int j = 0; j < 2; j++) {
            int kc = kc0 + j;
            int smoff = (row0 * SAH + kc * 8) * 2;
            // A
            int ra = bm + row0;
            const __half* ga = A + (size_t)(ra < M ? ra : 0) * K + k0 + kc * 8;
            cp16(smem_u32(&As[buf][0]) + smoff, ga, ra < M ? 16 : 0);
            // B
            int rb = bn + row0;
            const __half* gb = Bt + (size_t)(rb < N ? rb : 0) * K + k0 + kc * 8;
            cp16(smem_u32(&Bs[buf][0]) + smoff, gb, rb < N ? 16 : 0);
        }
        asm volatile("cp.async.commit_group;\n");
    };

    stage(0, 0);

    for (int it = 0; it < niter; it++) {
        if (it + 1 < niter) {
            stage((it + 1) & 1, (it + 1) * TBK);
            asm volatile("cp.async.wait_group 1;\n");
        } else {
            asm volatile("cp.async.wait_group 0;\n");
        }
        __syncthreads();

        int buf = it & 1;
        #pragma unroll
        for (int kk = 0; kk < 2; kk++) {
            int kb = kk * 16;
            unsigned af[4][4];
            #pragma unroll
            for (int mi = 0; mi < 4; mi++) {
                const __half* ap = &As[buf][(wm + mi * 16 + r) * SAH + kb + 2 * c];
                af[mi][0] = *(const unsigned*)(ap);
                af[mi][1] = *(const unsigned*)(ap + 8 * SAH);
                af[mi][2] = *(const unsigned*)(ap + 8);
                af[mi][3] = *(const unsigned*)(ap + 8 * SAH + 8);
            }
            unsigned bf[4][2];
            #pragma unroll
            for (int ni = 0; ni < 4; ni++) {
                const __half* bp = &Bs[buf][(wn + ni * 8 + r) * SAH + kb + 2 * c];
                bf[ni][0] = *(const unsigned*)(bp);
                bf[ni][1] = *(const unsigned*)(bp + 8);
            }
            #pragma unroll
            for (int mi = 0; mi < 4; mi++)
                #pragma unroll
                for (int ni = 0; ni < 4; ni++)
                    mma_f16(acc[mi][ni], af[mi], bf[ni]);
        }
        __syncthreads();
    }

    // epilogue: fp32 stores (float2 pairs)
    #pragma unroll
    for (int mi = 0; mi < 4; mi++) {
        int m0 = bm + wm + mi * 16 + r;
        #pragma unroll
        for (int ni = 0; ni < 4; ni++) {
            int n0 = bn + wn + ni * 8 + 2 * c;
            if (n0 < N) {
                if (m0 < M) {
                    float2 v = make_float2(acc[mi][ni][0], acc[mi][ni][1]);
                    *(float2*)&C[(size_t)m0 * N + n0] = v;
                }
                if (m0 + 8 < M) {
                    float2 v = make_float2(acc[mi][ni][2], acc[mi][ni][3]);
                    *(float2*)&C[(size_t)(m0 + 8) * N + n0] = v;
                }
            }
        }
    }
}

// ---- per-node attention logits -------------------------------------------
__global__ void node_alpha_kernel(const float* __restrict__ h,
                                  const float* __restrict__ a_s,
                                  const float* __restrict__ a_d,
                                  float* __restrict__ out_s,
                                  float* __restrict__ out_d,
                                  int H, int C) {
    int warp = (blockIdx.x * blockDim.x + threadIdx.x) >> 5;
    int lane = threadIdx.x & 31;
    if (warp >= NN * H) return;
    int n = warp / H;
    int hd = warp - n * H;
    const float* hp  = h + (size_t)n * H * C + (size_t)hd * C;
    const float* asv = a_s + (size_t)hd * C;
    const float* adv = a_d + (size_t)hd * C;
    float s = 0.f, d = 0.f;
    for (int cc = lane; cc < C; cc += 32) {
        float v = hp[cc];
        s = fmaf(v, asv[cc], s);
        d = fmaf(v, adv[cc], d);
    }
    #pragma unroll
    for (int o = 16; o > 0; o >>= 1) {
        s += __shfl_xor_sync(0xffffffffu, s, o);
        d += __shfl_xor_sync(0xffffffffu, d, o);
    }
    if (lane == 0) {
        out_s[n * H + hd] = s;
        out_d[n * H + hd] = d;
    }
}

// ---- edge softmax ---------------------------------------------------------
__device__ __forceinline__ float leaky(float x) {
    return x > 0.f ? x : NEG_SLOPE * x;
}

__global__ void edge_softmax_kernel(const int* __restrict__ rowptr,
                                    const int* __restrict__ csrsrc,
                                    const float* __restrict__ as_,
                                    const float* __restrict__ ad_,
                                    float* __restrict__ alpha, int H) {
    int warp = (blockIdx.x * blockDim.x + threadIdx.x) >> 5;
    int lane = threadIdx.x & 31;
    if (warp >= NN * H) return;
    int d = warp / H;
    int hd = warp - d * H;
    int s0 = rowptr[d], s1 = rowptr[d + 1];
    float adv = ad_[d * H + hd];

    float mx = -3.0e38f;
    for (int p = s0 + lane; p < s1; p += 32) {
        float e = leaky(as_[csrsrc[p] * H + hd] + adv);
        mx = fmaxf(mx, e);
    }
    #pragma unroll
    for (int o = 16; o > 0; o >>= 1)
        mx = fmaxf(mx, __shfl_xor_sync(0xffffffffu, mx, o));

    float sum = 0.f;
    for (int p = s0 + lane; p < s1; p += 32) {
        float e = leaky(as_[csrsrc[p] * H + hd] + adv);
        float ex = expf(e - mx);
        alpha[(size_t)p * H + hd] = ex;
        sum += ex;
    }
    #pragma unroll
    for (int o = 16; o > 0; o >>= 1)
        sum += __shfl_xor_sync(0xffffffffu, sum, o);
    float inv = 1.f / sum;

    for (int p = s0 + lane; p < s1; p += 32)
        alpha[(size_t)p * H + hd] *= inv;
}

// ---- aggregation: out = relu(sum alpha*h + b), fp16 or fp32 output --------
template <bool F16OUT>
__global__ __launch_bounds__(256)
void aggregate_kernel(const float* __restrict__ h,
                      const float* __restrict__ alpha,
                      const int* __restrict__ rowptr,
                      const int* __restrict__ csrsrc,
                      const float* __restrict__ bias,
                      float* __restrict__ out32,
                      __half* __restrict__ out16,
                      int H, int HC, int logC) {
    int d = blockIdx.x * blockDim.y + threadIdx.y;
    if (d >= NN) return;
    int f = threadIdx.x * 4;
    int head = f >> logC;

    float4 acc = make_float4(0.f, 0.f, 0.f, 0.f);
    int s0 = rowptr[d], s1 = rowptr[d + 1];
    for (int p = s0; p < s1; p++) {
        int src = csrsrc[p];
        float a = alpha[(size_t)p * H + head];
        float4 v = *(const float4*)&h[(size_t)src * HC + f];
        acc.x = fmaf(v.x, a, acc.x);
        acc.y = fmaf(v.y, a, acc.y);
        acc.z = fmaf(v.z, a, acc.z);
        acc.w = fmaf(v.w, a, acc.w);
    }
    float4 b = *(const float4*)&bias[f];
    float ox = fmaxf(acc.x + b.x, 0.f);
    float oy = fmaxf(acc.y + b.y, 0.f);
    float oz = fmaxf(acc.z + b.z, 0.f);
    float ow = fmaxf(acc.w + b.w, 0.f);
    if (F16OUT) {
        __half2 lo = __floats2half2_rn(ox, oy);
        __half2 hi = __floats2half2_rn(oz, ow);
        *(__half2*)&out16[(size_t)d * HC + f] = lo;
        *(__half2*)&out16[(size_t)d * HC + f + 2] = hi;
    } else {
        float4 o = make_float4(ox, oy, oz, ow);
        *(float4*)&out32[(size_t)d * HC + f] = o;
    }
}

// ---------------------------------------------------------------------------
// host side
// ---------------------------------------------------------------------------
static inline void run_gemm(const __half* A, const __half* Bt, float* C,
                            int M, int N, int K) {
    dim3 grid((N + TBN - 1) / TBN, (M + TBM - 1) / TBM);
    h16gemm_kernel<<<grid, 256>>>(A, Bt, C, M, N, K);
}

static inline void run_aggregate(const float* h, const float* alpha,
                                 const int* rowptr, const int* csrsrc,
                                 const float* bias, float* out32,
                                 __half* out16, int H, int HC, int logC) {
    int tx = HC / 4;
    int ty = 256 / tx;
    dim3 block(tx, ty);
    dim3 grid((NN + ty - 1) / ty);
    if (out16)
        aggregate_kernel<true><<<grid, block>>>(h, alpha, rowptr, csrsrc,
                                                bias, nullptr, out16, H, HC, logC);
    else
        aggregate_kernel<false><<<grid, block>>>(h, alpha, rowptr, csrsrc,
                                                 bias, out32, nullptr, H, HC, logC);
}

static inline void run_transpose(const float* W, __half* Wt, int K, int N) {
    dim3 grid((N + 31) / 32, (K + 31) / 32);
    transpose_w_kernel<<<grid, dim3(32, 8)>>>(W, Wt, K, N);
}

extern "C" void kernel_launch(void* const* d_in, const int* in_sizes, int n_in,
                              void* d_out, int out_size) {
    const float* x   = (const float*)d_in[0];
    const void*  ei  = d_in[1];
    const float* W1  = (const float*)d_in[2];
    const float* a1s = (const float*)d_in[3];
    const float* a1d = (const float*)d_in[4];
    const float* b1  = (const float*)d_in[5];
    const float* W2  = (const float*)d_in[6];
    const float* a2s = (const float*)d_in[7];
    const float* a2d = (const float*)d_in[8];
    const float* b2  = (const float*)d_in[9];
    const float* W3  = (const float*)d_in[10];
    const float* a3s = (const float*)d_in[11];
    const float* a3d = (const float*)d_in[12];
    const float* b3  = (const float*)d_in[13];
    const float* W4  = (const float*)d_in[14];
    const float* a4s = (const float*)d_in[15];
    const float* a4d = (const float*)d_in[16];
    const float* b4  = (const float*)d_in[17];
    float* out = (float*)d_out;

    float *bufB, *asb, *adb, *alpha;
    __half *hA, *hB, *wt;
    int *deg, *rowptr, *cursor, *csrsrc, *is64;
    cudaGetSymbolAddress((void**)&bufB, g_bufB);
    cudaGetSymbolAddress((void**)&hA, g_hA);
    cudaGetSymbolAddress((void**)&hB, g_hB);
    cudaGetSymbolAddress((void**)&wt, g_wt);
    cudaGetSymbolAddress((void**)&asb, g_as);
    cudaGetSymbolAddress((void**)&adb, g_ad);
    cudaGetSymbolAddress((void**)&alpha, g_alpha);
    cudaGetSymbolAddress((void**)&deg, g_deg);
    cudaGetSymbolAddress((void**)&rowptr, g_rowptr);
    cudaGetSymbolAddress((void**)&cursor, g_cursor);
    cudaGetSymbolAddress((void**)&csrsrc, g_csrsrc);
    cudaGetSymbolAddress((void**)&is64, g_is64);

    __half* wt1 = wt;                     // [512][256]
    __half* wt2 = wt + 131072;            // [512][512]
    __half* wt3 = wt + 131072 + 262144;   // [256][512]
    __half* wt4 = wt + 131072 + 262144 + 131072;  // [64][256]

    // ---- prep: CSR + dtype conversions (graph identical across layers) ----
    cudaMemsetAsync(deg, 0, NN * sizeof(int));
    detect64_kernel<<<1, 32>>>((const int*)ei, is64);
    count_deg_kernel<<<(E_TOT + 255) / 256, 256>>>(ei, is64, deg);
    scan_kernel<<<1, 1024>>>(deg, rowptr, NN);
    cudaMemcpyAsync(cursor, rowptr, NN * sizeof(int), cudaMemcpyDeviceToDevice);
    fill_csr_kernel<<<(E_TOT + 255) / 256, 256>>>(ei, is64, cursor, csrsrc);

    f2h_kernel<<<(NN * 256 / 4 + 255) / 256, 256>>>(x, hA, NN * 256);
    run_transpose(W1, wt1, 256, 512);
    run_transpose(W2, wt2, 512, 512);
    run_transpose(W3, wt3, 512, 256);
    run_transpose(W4, wt4, 256, 64);

    auto nblocks_warps = [](int warps) { return (warps + 7) / 8; };

    // ---- layer 1: 256 -> 4x128 ----
    run_gemm(hA, wt1, bufB, NN, 512, 256);
    node_alpha_kernel<<<nblocks_warps(NN * 4), 256>>>(bufB, a1s, a1d, asb, adb, 4, 128);
    edge_softmax_kernel<<<nblocks_warps(NN * 4), 256>>>(rowptr, csrsrc, asb, adb, alpha, 4);
    run_aggregate(bufB, alpha, rowptr, csrsrc, b1, nullptr, hB, 4, 512, 7);

    // ---- layer 2: 512 -> 4x128 ----
    run_gemm(hB, wt2, bufB, NN, 512, 512);
    node_alpha_kernel<<<nblocks_warps(NN * 4), 256>>>(bufB, a2s, a2d, asb, adb, 4, 128);
    edge_softmax_kernel<<<nblocks_warps(NN * 4), 256>>>(rowptr, csrsrc, asb, adb, alpha, 4);
    run_aggregate(bufB, alpha, rowptr, csrsrc, b2, nullptr, hA, 4, 512, 7);

    // ---- layer 3: 512 -> 4x64 ----
    run_gemm(hA, wt3, bufB, NN, 256, 512);
    node_alpha_kernel<<<nblocks_warps(NN * 4), 256>>>(bufB, a3s, a3d, asb, adb, 4, 64);
    edge_softmax_kernel<<<nblocks_warps(NN * 4), 256>>>(rowptr, csrsrc, asb, adb, alpha, 4);
    run_aggregate(bufB, alpha, rowptr, csrsrc, b3, nullptr, hB, 4, 256, 6);

    // ---- layer 4: 256 -> 1x64, concat=False ----
    run_gemm(hB, wt4, bufB, NN, 64, 256);
    node_alpha_kernel<<<nblocks_warps(NN * 1), 256>>>(bufB, a4s, a4d, asb, adb, 1, 64);
    edge_softmax_kernel<<<nblocks_warps(NN * 1), 256>>>(rowptr, csrsrc, asb, adb, alpha, 1);
    run_aggregate(bufB, alpha, rowptr, csrsrc, b4, out, nullptr, 1, 64, 6);

    (void)in_sizes; (void)n_in; (void)out_size;
}